// round 16
// baseline (speedup 1.0000x reference)
#include <cuda_runtime.h>
#include <cuda_fp16.h>
#include <math.h>
#include <stdint.h>

#define B_  4
#define L_  2048
#define D_  2048
#define H_  16
#define HD_ 128
#define M_  (B_ * L_)   // 8192
#define E3_ (3 * D_)    // 6144

// ---------------- scratch (allocation-free rule) ----------------
__device__ __half g_qkv16[(size_t)M_ * E3_];
__device__ __half g_x16[(size_t)M_ * D_];
__device__ __half g_wq16[(size_t)E3_ * D_];
__device__ __half g_wo16[(size_t)D_ * D_];
__device__ __half g_y16[(size_t)M_ * D_];
__device__ __half g_vt16[(size_t)M_ * D_];
__device__ float g_cos[L_ * 64], g_sin[L_ * 64];

// ---------------- helpers ----------------
__device__ __forceinline__ uint32_t smem_u32(const void* p) {
    uint32_t a;
    asm("{ .reg .u64 t; cvta.to.shared.u64 t, %1; cvt.u32.u64 %0, t; }" : "=r"(a) : "l"(p));
    return a;
}
#define CP16(dst, src)  asm volatile("cp.async.cg.shared.global [%0], [%1], 16;" :: "r"(dst), "l"(src) : "memory")
#define CP_COMMIT()     asm volatile("cp.async.commit_group;" ::: "memory")
#define CP_WAIT0()      asm volatile("cp.async.wait_group 0;" ::: "memory")
#define CP_WAIT1()      asm volatile("cp.async.wait_group 1;" ::: "memory")
#define CP_WAIT2()      asm volatile("cp.async.wait_group 2;" ::: "memory")
#define SWZ(o) ((o) ^ (((o) >> 3) & 0x70))

#define LDSM4(r0, r1, r2, r3, addr) \
    asm volatile("ldmatrix.sync.aligned.m8n8.x4.shared.b16 {%0,%1,%2,%3}, [%4];" \
        : "=r"(r0), "=r"(r1), "=r"(r2), "=r"(r3) : "r"(addr))

__device__ __forceinline__ void mma_f16(float* c, const uint32_t* a, uint32_t b0, uint32_t b1) {
    asm volatile(
        "mma.sync.aligned.m16n8k16.row.col.f32.f16.f16.f32 "
        "{%0,%1,%2,%3}, {%4,%5,%6,%7}, {%8,%9}, {%0,%1,%2,%3};"
        : "+f"(c[0]), "+f"(c[1]), "+f"(c[2]), "+f"(c[3])
        : "r"(a[0]), "r"(a[1]), "r"(a[2]), "r"(a[3]), "r"(b0), "r"(b1));
}

__device__ __forceinline__ uint32_t pack_f16(float a, float b) {
    __half2 t = __floats2half2_rn(a, b);
    return *reinterpret_cast<uint32_t*>(&t);
}

// ---------------------------------------------------------------------------
// Fused prep: all fp32->fp16 conversions + rope table in ONE launch.
// ---------------------------------------------------------------------------
#define PREP_N1 (M_ * D_ / 4)
#define PREP_N2 (PREP_N1 + E3_ * D_ / 4)
#define PREP_N3 (PREP_N2 + D_ * D_ / 4)
#define PREP_N4 (PREP_N3 + L_ * 64)

__device__ __forceinline__ void cvt4(const float* __restrict__ x,
                                     __half* __restrict__ o, int i) {
    float4 v = ((const float4*)x)[i];
    ((__half2*)o)[2 * i]     = __floats2half2_rn(v.x, v.y);
    ((__half2*)o)[2 * i + 1] = __floats2half2_rn(v.z, v.w);
}

__global__ void prep_all(const float* __restrict__ x,
                         const float* __restrict__ wq,
                         const float* __restrict__ wo,
                         __half* __restrict__ x16,
                         __half* __restrict__ wq16,
                         __half* __restrict__ wo16,
                         float* __restrict__ ct, float* __restrict__ st)
{
    int i = blockIdx.x * blockDim.x + threadIdx.x;
    if (i < PREP_N1) {
        cvt4(x, x16, i);
    } else if (i < PREP_N2) {
        cvt4(wq, wq16, i - PREP_N1);
    } else if (i < PREP_N3) {
        cvt4(wo, wo16, i - PREP_N2);
    } else if (i < PREP_N4) {
        int idx = i - PREP_N3;
        int l = idx >> 6, ii = idx & 63;
        const double LN1E4_OVER_64 = 0.14391156831212787;
        double invf = exp(-(double)ii * LN1E4_OVER_64);
        double ang  = (double)l * invf;
        const double TWO_PI = 6.283185307179586476925286766559;
        ang -= TWO_PI * floor(ang / TWO_PI);
        float s, c;
        sincosf((float)ang, &s, &c);
        ct[idx] = c; st[idx] = s;
    }
}

// ---------------------------------------------------------------------------
// fp16 single-term GEMM (R13/R14-proven): C[M,N] = A[M,K] * B[N,K]^T
// CTA 128x256, BK=64, 8 warps, 4-stage cp.async, 1 barrier/chunk, supertiled.
// MODE 0: fp32 C epilogue.  MODE 1: fused RoPE + fp16 qkv epilogue.
// ---------------------------------------------------------------------------
#define BM 128
#define BN 256
#define BK 64
#define GM 16
#define STG1 49152
#define GEMM_SMEM (4 * STG1)

template<int MODE>
__global__ __launch_bounds__(256, 1) void gemm_f16(
    const __half* __restrict__ A, const __half* __restrict__ Bm,
    float* __restrict__ C, __half* __restrict__ O16,
    const float* __restrict__ ct, const float* __restrict__ st_,
    int M, int N, int K)
{
    extern __shared__ char smem[];
    const uint32_t sb = smem_u32(smem);
    const int tid  = threadIdx.x;
    const int wid  = tid >> 5;
    const int lane = tid & 31;
    const int wm = wid & 1;
    const int wn = wid >> 1;

    const int nm = M / BM, nn = N / BN;
    int bid = blockIdx.x;
    int per = GM * nn;
    int grp = bid / per, r = bid % per;
    int mstart = grp * GM;
    int gsize = min(GM, nm - mstart);
    const int bm = (mstart + r % gsize) * BM;
    const int bn = (r / gsize) * BN;

    const int NC = K / BK;

    const __half* gA = A  + (size_t)bm * K;
    const __half* gB = Bm + (size_t)bn * K;

    const int lr0 = tid >> 3;
    const int lc  = tid & 7;

    auto load_chunk = [&](int ic) {
        const uint32_t st = sb + (ic & 3) * STG1;
        const size_t k0 = (size_t)ic * BK;
        #pragma unroll
        for (int it = 0; it < 4; it++) {
            int rr = lr0 + it * 32;
            uint32_t off = SWZ((uint32_t)(rr * 128 + lc * 16));
            CP16(st + off, gA + (size_t)rr * K + k0 + lc * 8);
        }
        #pragma unroll
        for (int it = 0; it < 8; it++) {
            int rr = lr0 + it * 32;
            uint32_t off = SWZ((uint32_t)(rr * 128 + lc * 16));
            CP16(st + 16384 + off, gB + (size_t)rr * K + k0 + lc * 8);
        }
        CP_COMMIT();
    };

    float acc[4][8][4];
    #pragma unroll
    for (int m = 0; m < 4; m++)
        #pragma unroll
        for (int n = 0; n < 8; n++)
            #pragma unroll
            for (int v = 0; v < 4; v++) acc[m][n][v] = 0.f;

    load_chunk(0);
    load_chunk(1);
    load_chunk(2);

    const int a_row = wm * 64 + (lane & 15);
    const int a_kb  = (lane >> 4) << 4;
    const int b_row = wn * 64 + (lane & 7) + ((lane >> 4) << 3);
    const int b_kb  = ((lane >> 3) & 1) << 4;

    for (int ic = 0; ic < NC; ic++) {
        const int rem = NC - 1 - ic;
        if (rem == 0) CP_WAIT0();
        else if (rem == 1) CP_WAIT1();
        else CP_WAIT2();
        __syncthreads();

        const uint32_t st = sb + (ic & 3) * STG1;

        #pragma unroll
        for (int ks = 0; ks < 4; ks++) {
            uint32_t a[4][4];
            #pragma unroll
            for (int m = 0; m < 4; m++) {
                uint32_t off = SWZ((uint32_t)((a_row + m * 16) * 128 + ks * 32 + a_kb));
                LDSM4(a[m][0], a[m][1], a[m][2], a[m][3], st + off);
            }
            #pragma unroll
            for (int p = 0; p < 4; p++) {
                uint32_t off = SWZ((uint32_t)((b_row + p * 16) * 128 + ks * 32 + b_kb));
                uint32_t bH[4];
                LDSM4(bH[0], bH[1], bH[2], bH[3], st + 16384 + off);
                #pragma unroll
                for (int m = 0; m < 4; m++) {
                    mma_f16(acc[m][2*p],   a[m], bH[0], bH[1]);
                    mma_f16(acc[m][2*p+1], a[m], bH[2], bH[3]);
                }
            }
        }
        if (ic + 3 < NC) load_chunk(ic + 3);
    }

    const int er = lane >> 2;
    const int ec = (lane & 3) * 2;

    if (MODE == 0) {
        #pragma unroll
        for (int m = 0; m < 4; m++) {
            int row0 = bm + wm * 64 + m * 16 + er;
            #pragma unroll
            for (int n = 0; n < 8; n++) {
                int col = bn + wn * 64 + n * 8 + ec;
                *(float2*)(C + (size_t)row0 * N + col)       = make_float2(acc[m][n][0], acc[m][n][1]);
                *(float2*)(C + (size_t)(row0 + 8) * N + col) = make_float2(acc[m][n][2], acc[m][n][3]);
            }
        }
    } else {
        const int part = bn >> 11;
        #pragma unroll
        for (int m = 0; m < 4; m++) {
            int rowa = bm + wm * 64 + m * 16 + er;
            #pragma unroll
            for (int rr = 0; rr < 2; rr++) {
                int row = rowa + rr * 8;
                int l = row & 2047;
                #pragma unroll
                for (int n = 0; n < 8; n++) {
                    int col = bn + wn * 64 + n * 8 + ec;
                    float v0 = acc[m][n][2 * rr], v1 = acc[m][n][2 * rr + 1];
                    if (part < 2) {
                        int i = (col & 127) >> 1;
                        float c = ct[l * 64 + i], s = st_[l * 64 + i];
                        float r0 = v0 * c - v1 * s;
                        float r1 = v1 * c + v0 * s;
                        v0 = r0; v1 = r1;
                    }
                    *(__half2*)(O16 + (size_t)row * E3_ + col) = __floats2half2_rn(v0, v1);
                }
            }
        }
    }
}

// ---------------------------------------------------------------------------
// V transpose (fp16 in/out): qkv16 v-part -> vt16 [b,h,128,l]
// ---------------------------------------------------------------------------
__global__ __launch_bounds__(256) void vtrans(const __half* __restrict__ qkv16,
                                              __half* __restrict__ vt16)
{
    __shared__ float vt[32][129];
    const int bh = blockIdx.y;
    const int b = bh >> 4, h = bh & 15;
    const int l0 = blockIdx.x * 32;
    const int tid = threadIdx.x;
    const int lane = tid & 31;
    const int hd0 = lane * 4;

    #pragma unroll
    for (int pass = 0; pass < 4; pass++) {
        int ll = (tid >> 5) + pass * 8;
        size_t src = (size_t)(b * L_ + l0 + ll) * E3_ + 2 * D_ + h * HD_ + hd0;
        __half2 a = *(const __half2*)(qkv16 + src);
        __half2 c = *(const __half2*)(qkv16 + src + 2);
        vt[ll][hd0]     = __half2float(a.x); vt[ll][hd0 + 1] = __half2float(a.y);
        vt[ll][hd0 + 2] = __half2float(c.x); vt[ll][hd0 + 3] = __half2float(c.y);
    }
    __syncthreads();

    const int r = tid >> 1;
    const int lh = (tid & 1) * 16;
    size_t vbase = ((size_t)bh * HD_ + r) * L_ + l0 + lh;
    #pragma unroll
    for (int j = 0; j < 16; j += 2) {
        *(__half2*)(vt16 + vbase + j) =
            __floats2half2_rn(vt[lh + j][r], vt[lh + j + 1][r]);
    }
}

// ---------------------------------------------------------------------------
// Flash attention, fp16 single-term mma. NOW: 128 threads / 4 warps / 64 q-rows
// per CTA -> SMEM 80KB, 2 CTAs per SM co-resident (softmax of one CTA overlaps
// MMA of the other). Same per-warp math as R12-R14 (bit-identical numerics).
// SMEM: Q 16KB | 2 stages x (K 16K | Vt 16K) = 80KB.
// ---------------------------------------------------------------------------
#define ATT_SMEM 81920

__global__ __launch_bounds__(128, 2) void flash_mma(
    const __half* __restrict__ qkv16, const __half* __restrict__ vt16,
    __half* __restrict__ y)
{
    extern __shared__ char smem[];
    const uint32_t sb = smem_u32(smem);
    const int tid = threadIdx.x, wid = tid >> 5, lane = tid & 31;
    const int bh = blockIdx.y;
    const int b = bh >> 4, h = bh & 15;
    const int q0 = (gridDim.x - 1 - blockIdx.x) * 64;   // heavy blocks first
    const int NB = q0 / 64 + 1;                          // tiles 0..q0/64 (last is diagonal)

    const __half* qb = qkv16 + (size_t)b * L_ * E3_ + h * HD_;
    const __half* kb = qb + D_;
    const size_t vbase = (size_t)bh * HD_ * L_;

    // Q: [half(c>=8)][64 rows][128B], 16KB
    #pragma unroll
    for (int it = 0; it < 8; it++) {
        int idx = tid + 128 * it;
        int c = idx & 15, r = idx >> 4;
        const __half* src = qb + (size_t)(q0 + r) * E3_ + c * 8;
        CP16(sb + (c >> 3) * 8192 + SWZ((uint32_t)(r * 128 + (c & 7) * 16)), src);
    }
    auto load_kv = [&](int kb_i, int s) {
        const uint32_t st0 = sb + 16384 + s * 32768;
        const int k0 = kb_i * 64;
        #pragma unroll
        for (int it = 0; it < 8; it++) {   // K: [half][64 rows][128B] = 16KB
            int idx = tid + 128 * it;
            int c = idx & 15, r = idx >> 4;
            const __half* src = kb + (size_t)(k0 + r) * E3_ + c * 8;
            CP16(st0 + (c >> 3) * 8192 + SWZ((uint32_t)(r * 128 + (c & 7) * 16)), src);
        }
        #pragma unroll
        for (int it = 0; it < 8; it++) {   // Vt: [128 hd][128B] = 16KB
            int idx = tid + 128 * it;
            int c = idx & 7, r = idx >> 3;
            const __half* src = vt16 + vbase + (size_t)r * L_ + k0 + c * 8;
            CP16(st0 + 16384 + SWZ((uint32_t)(r * 128 + c * 16)), src);
        }
        CP_COMMIT();
    };

    load_kv(0, 0);
    if (NB > 1) load_kv(1, 1);

    float o[16][4];
    #pragma unroll
    for (int n = 0; n < 16; n++)
        #pragma unroll
        for (int v = 0; v < 4; v++) o[n][v] = 0.f;
    float m0 = -1e30f, m1 = -1e30f, l0 = 0.f, l1 = 0.f;

    const int a_row = wid * 16 + (lane & 15);
    const uint32_t a_kb = (lane >> 4) << 4;
    const int b_row = (lane & 7) + ((lane >> 4) << 3);
    const uint32_t b_kb = ((lane >> 3) & 1) << 4;
    const float scale = 0.08838834764831845f;
    const int row0 = q0 + wid * 16 + (lane >> 2);
    const int ec = (lane & 3) * 2;

    for (int kbi = 0; kbi < NB; kbi++) {
        const int s = kbi & 1;
        if (kbi == NB - 1) CP_WAIT0(); else CP_WAIT1();
        __syncthreads();
        const uint32_t st0 = sb + 16384 + s * 32768;
        const int k0 = kbi * 64;

        // ---- S = Q K^T ----
        float sc[8][4];
        #pragma unroll
        for (int n = 0; n < 8; n++)
            #pragma unroll
            for (int v = 0; v < 4; v++) sc[n][v] = 0.f;

        #pragma unroll
        for (int half = 0; half < 2; half++)
            #pragma unroll
            for (int ks = 0; ks < 4; ks++) {
                uint32_t qo = sb + half * 8192 + SWZ((uint32_t)(a_row * 128 + ks * 32 + a_kb));
                uint32_t aQ[4];
                LDSM4(aQ[0], aQ[1], aQ[2], aQ[3], qo);
                #pragma unroll
                for (int p = 0; p < 4; p++) {
                    uint32_t ko = st0 + half * 8192 + SWZ((uint32_t)((b_row + p * 16) * 128 + ks * 32 + b_kb));
                    uint32_t bH[4];
                    LDSM4(bH[0], bH[1], bH[2], bH[3], ko);
                    mma_f16(sc[2*p],   aQ, bH[0], bH[1]);
                    mma_f16(sc[2*p+1], aQ, bH[2], bH[3]);
                }
            }

        const bool need_mask = (kbi == NB - 1);   // only diagonal tile
        #pragma unroll
        for (int n = 0; n < 8; n++)
            #pragma unroll
            for (int v = 0; v < 4; v++) {
                float val = sc[n][v] * scale;
                if (need_mask) {
                    int col = k0 + n * 8 + ec + (v & 1);
                    int row = row0 + ((v >= 2) ? 8 : 0);
                    if (col > row) val = -1e30f;
                }
                sc[n][v] = val;
            }

        float mx0 = -1e30f, mx1 = -1e30f;
        #pragma unroll
        for (int n = 0; n < 8; n++) {
            mx0 = fmaxf(mx0, fmaxf(sc[n][0], sc[n][1]));
            mx1 = fmaxf(mx1, fmaxf(sc[n][2], sc[n][3]));
        }
        mx0 = fmaxf(mx0, __shfl_xor_sync(0xffffffffu, mx0, 1));
        mx0 = fmaxf(mx0, __shfl_xor_sync(0xffffffffu, mx0, 2));
        mx1 = fmaxf(mx1, __shfl_xor_sync(0xffffffffu, mx1, 1));
        mx1 = fmaxf(mx1, __shfl_xor_sync(0xffffffffu, mx1, 2));
        float nm0 = fmaxf(m0, mx0), nm1 = fmaxf(m1, mx1);
        float al0 = __expf(m0 - nm0), al1 = __expf(m1 - nm1);
        m0 = nm0; m1 = nm1;
        float ps0 = 0.f, ps1 = 0.f;
        #pragma unroll
        for (int n = 0; n < 8; n++) {
            float p0 = __expf(sc[n][0] - m0), p1 = __expf(sc[n][1] - m0);
            float p2 = __expf(sc[n][2] - m1), p3 = __expf(sc[n][3] - m1);
            sc[n][0] = p0; sc[n][1] = p1; sc[n][2] = p2; sc[n][3] = p3;
            ps0 += p0 + p1; ps1 += p2 + p3;
        }
        l0 = l0 * al0 + ps0;
        l1 = l1 * al1 + ps1;
        #pragma unroll
        for (int n = 0; n < 16; n++) {
            o[n][0] *= al0; o[n][1] *= al0; o[n][2] *= al1; o[n][3] *= al1;
        }

        // ---- O += P V ----
        #pragma unroll
        for (int kc = 0; kc < 4; kc++) {
            uint32_t aP[4];
            aP[0] = pack_f16(sc[2*kc][0],   sc[2*kc][1]);
            aP[1] = pack_f16(sc[2*kc][2],   sc[2*kc][3]);
            aP[2] = pack_f16(sc[2*kc+1][0], sc[2*kc+1][1]);
            aP[3] = pack_f16(sc[2*kc+1][2], sc[2*kc+1][3]);
            #pragma unroll
            for (int p = 0; p < 8; p++) {
                uint32_t vo = st0 + 16384 + SWZ((uint32_t)((b_row + p * 16) * 128 + kc * 32 + b_kb));
                uint32_t bH[4];
                LDSM4(bH[0], bH[1], bH[2], bH[3], vo);
                mma_f16(o[2*p],   aP, bH[0], bH[1]);
                mma_f16(o[2*p+1], aP, bH[2], bH[3]);
            }
        }
        __syncthreads();
        if (kbi + 2 < NB) load_kv(kbi + 2, s);
    }

    l0 += __shfl_xor_sync(0xffffffffu, l0, 1);
    l0 += __shfl_xor_sync(0xffffffffu, l0, 2);
    l1 += __shfl_xor_sync(0xffffffffu, l1, 1);
    l1 += __shfl_xor_sync(0xffffffffu, l1, 2);
    float i0 = 1.f / l0, i1 = 1.f / l1;
    const size_t rbase = (size_t)(b * L_ + row0) * D_ + h * HD_ + ec;
    #pragma unroll
    for (int n = 0; n < 16; n++) {
        size_t o0 = rbase + n * 8;
        size_t o1 = o0 + 8 * (size_t)D_;
        *(__half2*)(y + o0) = __floats2half2_rn(o[n][0] * i0, o[n][1] * i0);
        *(__half2*)(y + o1) = __floats2half2_rn(o[n][2] * i1, o[n][3] * i1);
    }
}

// ---------------------------------------------------------------------------
extern "C" void kernel_launch(void* const* d_in, const int* in_sizes, int n_in,
                              void* d_out, int out_size)
{
    const float* x     = (const float*)d_in[0];
    const float* w_qkv = (const float*)d_in[1];
    const float* w_o   = (const float*)d_in[2];
    float* out = (float*)d_out;

    float *ct, *st;
    __half *qkv16, *x16, *wq16, *wo16, *y16, *vt16;
    cudaGetSymbolAddress((void**)&qkv16, g_qkv16);
    cudaGetSymbolAddress((void**)&ct,    g_cos); cudaGetSymbolAddress((void**)&st, g_sin);
    cudaGetSymbolAddress((void**)&x16,   g_x16);
    cudaGetSymbolAddress((void**)&wq16,  g_wq16);
    cudaGetSymbolAddress((void**)&wo16,  g_wo16);
    cudaGetSymbolAddress((void**)&y16,   g_y16);
    cudaGetSymbolAddress((void**)&vt16,  g_vt16);

    cudaFuncSetAttribute(gemm_f16<0>, cudaFuncAttributeMaxDynamicSharedMemorySize, GEMM_SMEM);
    cudaFuncSetAttribute(gemm_f16<1>, cudaFuncAttributeMaxDynamicSharedMemorySize, GEMM_SMEM);
    cudaFuncSetAttribute(flash_mma,   cudaFuncAttributeMaxDynamicSharedMemorySize, ATT_SMEM);

    // fused prep (all conversions + rope table, one launch)
    prep_all<<<(PREP_N4 + 255) / 256, 256>>>(x, w_qkv, w_o, x16, wq16, wo16, ct, st);

    // 1) qkv = x @ w_qkv^T, fused RoPE + fp16 store
    gemm_f16<1><<<(M_ / BM) * (E3_ / BN), 256, GEMM_SMEM>>>(
        x16, wq16, nullptr, qkv16, ct, st, M_, E3_, D_);

    // 2) V transpose (fp16)
    vtrans<<<dim3(L_ / 32, B_ * H_), 256>>>(qkv16, vt16);

    // 3) causal flash attention (64 q-rows/CTA, 2 CTAs/SM) -> y fp16
    flash_mma<<<dim3(L_ / 64, B_ * H_), 128, ATT_SMEM>>>(qkv16, vt16, y16);

    // 4) out = y @ w_o^T (fp32 out)
    gemm_f16<0><<<(M_ / BM) * (D_ / BN), 256, GEMM_SMEM>>>(
        y16, wo16, out, nullptr, nullptr, nullptr, M_, D_, D_);
}

// round 17
// speedup vs baseline: 1.0026x; 1.0026x over previous
#include <cuda_runtime.h>
#include <cuda_fp16.h>
#include <math.h>
#include <stdint.h>

#define B_  4
#define L_  2048
#define D_  2048
#define H_  16
#define HD_ 128
#define M_  (B_ * L_)   // 8192
#define E3_ (3 * D_)    // 6144

// scale(1/sqrt(128)) * log2(e): folded into Q at the qkv epilogue
#define QSCALE 0.12751744249055825f

// ---------------- scratch (allocation-free rule) ----------------
__device__ __half g_qkv16[(size_t)M_ * E3_];
__device__ __half g_x16[(size_t)M_ * D_];
__device__ __half g_wq16[(size_t)E3_ * D_];
__device__ __half g_wo16[(size_t)D_ * D_];
__device__ __half g_y16[(size_t)M_ * D_];
__device__ __half g_vt16[(size_t)M_ * D_];
__device__ float g_cos[L_ * 64], g_sin[L_ * 64];

// ---------------- helpers ----------------
__device__ __forceinline__ uint32_t smem_u32(const void* p) {
    uint32_t a;
    asm("{ .reg .u64 t; cvta.to.shared.u64 t, %1; cvt.u32.u64 %0, t; }" : "=r"(a) : "l"(p));
    return a;
}
#define CP16(dst, src)  asm volatile("cp.async.cg.shared.global [%0], [%1], 16;" :: "r"(dst), "l"(src) : "memory")
#define CP_COMMIT()     asm volatile("cp.async.commit_group;" ::: "memory")
#define CP_WAIT0()      asm volatile("cp.async.wait_group 0;" ::: "memory")
#define CP_WAIT1()      asm volatile("cp.async.wait_group 1;" ::: "memory")
#define CP_WAIT2()      asm volatile("cp.async.wait_group 2;" ::: "memory")
#define SWZ(o) ((o) ^ (((o) >> 3) & 0x70))

#define LDSM4(r0, r1, r2, r3, addr) \
    asm volatile("ldmatrix.sync.aligned.m8n8.x4.shared.b16 {%0,%1,%2,%3}, [%4];" \
        : "=r"(r0), "=r"(r1), "=r"(r2), "=r"(r3) : "r"(addr))

__device__ __forceinline__ void mma_f16(float* c, const uint32_t* a, uint32_t b0, uint32_t b1) {
    asm volatile(
        "mma.sync.aligned.m16n8k16.row.col.f32.f16.f16.f32 "
        "{%0,%1,%2,%3}, {%4,%5,%6,%7}, {%8,%9}, {%0,%1,%2,%3};"
        : "+f"(c[0]), "+f"(c[1]), "+f"(c[2]), "+f"(c[3])
        : "r"(a[0]), "r"(a[1]), "r"(a[2]), "r"(a[3]), "r"(b0), "r"(b1));
}

__device__ __forceinline__ uint32_t pack_f16(float a, float b) {
    __half2 t = __floats2half2_rn(a, b);
    return *reinterpret_cast<uint32_t*>(&t);
}

// ---------------------------------------------------------------------------
// Fused prep: all fp32->fp16 conversions + rope table in ONE launch.
// ---------------------------------------------------------------------------
#define PREP_N1 (M_ * D_ / 4)
#define PREP_N2 (PREP_N1 + E3_ * D_ / 4)
#define PREP_N3 (PREP_N2 + D_ * D_ / 4)
#define PREP_N4 (PREP_N3 + L_ * 64)

__device__ __forceinline__ void cvt4(const float* __restrict__ x,
                                     __half* __restrict__ o, int i) {
    float4 v = ((const float4*)x)[i];
    ((__half2*)o)[2 * i]     = __floats2half2_rn(v.x, v.y);
    ((__half2*)o)[2 * i + 1] = __floats2half2_rn(v.z, v.w);
}

__global__ void prep_all(const float* __restrict__ x,
                         const float* __restrict__ wq,
                         const float* __restrict__ wo,
                         __half* __restrict__ x16,
                         __half* __restrict__ wq16,
                         __half* __restrict__ wo16,
                         float* __restrict__ ct, float* __restrict__ st)
{
    int i = blockIdx.x * blockDim.x + threadIdx.x;
    if (i < PREP_N1) {
        cvt4(x, x16, i);
    } else if (i < PREP_N2) {
        cvt4(wq, wq16, i - PREP_N1);
    } else if (i < PREP_N3) {
        cvt4(wo, wo16, i - PREP_N2);
    } else if (i < PREP_N4) {
        int idx = i - PREP_N3;
        int l = idx >> 6, ii = idx & 63;
        const double LN1E4_OVER_64 = 0.14391156831212787;
        double invf = exp(-(double)ii * LN1E4_OVER_64);
        double ang  = (double)l * invf;
        const double TWO_PI = 6.283185307179586476925286766559;
        ang -= TWO_PI * floor(ang / TWO_PI);
        float s, c;
        sincosf((float)ang, &s, &c);
        ct[idx] = c; st[idx] = s;
    }
}

// ---------------------------------------------------------------------------
// fp16 single-term GEMM: C[M,N] = A[M,K] * B[N,K]^T
// CTA 128x256, BK=64, 8 warps, 4-stage cp.async, 1 barrier/chunk, supertiled.
// MODE 0: fp32 C epilogue.
// MODE 1: fused RoPE + fp16 qkv epilogue; Q additionally scaled by QSCALE
//         (softmax scale * log2e) so flash can use pure exp2.
// ---------------------------------------------------------------------------
#define BM 128
#define BN 256
#define BK 64
#define GM 16
#define STG1 49152
#define GEMM_SMEM (4 * STG1)

template<int MODE>
__global__ __launch_bounds__(256, 1) void gemm_f16(
    const __half* __restrict__ A, const __half* __restrict__ Bm,
    float* __restrict__ C, __half* __restrict__ O16,
    const float* __restrict__ ct, const float* __restrict__ st_,
    int M, int N, int K)
{
    extern __shared__ char smem[];
    const uint32_t sb = smem_u32(smem);
    const int tid  = threadIdx.x;
    const int wid  = tid >> 5;
    const int lane = tid & 31;
    const int wm = wid & 1;
    const int wn = wid >> 1;

    const int nm = M / BM, nn = N / BN;
    int bid = blockIdx.x;
    int per = GM * nn;
    int grp = bid / per, r = bid % per;
    int mstart = grp * GM;
    int gsize = min(GM, nm - mstart);
    const int bm = (mstart + r % gsize) * BM;
    const int bn = (r / gsize) * BN;

    const int NC = K / BK;

    const __half* gA = A  + (size_t)bm * K;
    const __half* gB = Bm + (size_t)bn * K;

    const int lr0 = tid >> 3;
    const int lc  = tid & 7;

    auto load_chunk = [&](int ic) {
        const uint32_t st = sb + (ic & 3) * STG1;
        const size_t k0 = (size_t)ic * BK;
        #pragma unroll
        for (int it = 0; it < 4; it++) {
            int rr = lr0 + it * 32;
            uint32_t off = SWZ((uint32_t)(rr * 128 + lc * 16));
            CP16(st + off, gA + (size_t)rr * K + k0 + lc * 8);
        }
        #pragma unroll
        for (int it = 0; it < 8; it++) {
            int rr = lr0 + it * 32;
            uint32_t off = SWZ((uint32_t)(rr * 128 + lc * 16));
            CP16(st + 16384 + off, gB + (size_t)rr * K + k0 + lc * 8);
        }
        CP_COMMIT();
    };

    float acc[4][8][4];
    #pragma unroll
    for (int m = 0; m < 4; m++)
        #pragma unroll
        for (int n = 0; n < 8; n++)
            #pragma unroll
            for (int v = 0; v < 4; v++) acc[m][n][v] = 0.f;

    load_chunk(0);
    load_chunk(1);
    load_chunk(2);

    const int a_row = wm * 64 + (lane & 15);
    const int a_kb  = (lane >> 4) << 4;
    const int b_row = wn * 64 + (lane & 7) + ((lane >> 4) << 3);
    const int b_kb  = ((lane >> 3) & 1) << 4;

    for (int ic = 0; ic < NC; ic++) {
        const int rem = NC - 1 - ic;
        if (rem == 0) CP_WAIT0();
        else if (rem == 1) CP_WAIT1();
        else CP_WAIT2();
        __syncthreads();

        const uint32_t st = sb + (ic & 3) * STG1;

        #pragma unroll
        for (int ks = 0; ks < 4; ks++) {
            uint32_t a[4][4];
            #pragma unroll
            for (int m = 0; m < 4; m++) {
                uint32_t off = SWZ((uint32_t)((a_row + m * 16) * 128 + ks * 32 + a_kb));
                LDSM4(a[m][0], a[m][1], a[m][2], a[m][3], st + off);
            }
            #pragma unroll
            for (int p = 0; p < 4; p++) {
                uint32_t off = SWZ((uint32_t)((b_row + p * 16) * 128 + ks * 32 + b_kb));
                uint32_t bH[4];
                LDSM4(bH[0], bH[1], bH[2], bH[3], st + 16384 + off);
                #pragma unroll
                for (int m = 0; m < 4; m++) {
                    mma_f16(acc[m][2*p],   a[m], bH[0], bH[1]);
                    mma_f16(acc[m][2*p+1], a[m], bH[2], bH[3]);
                }
            }
        }
        if (ic + 3 < NC) load_chunk(ic + 3);
    }

    const int er = lane >> 2;
    const int ec = (lane & 3) * 2;

    if (MODE == 0) {
        #pragma unroll
        for (int m = 0; m < 4; m++) {
            int row0 = bm + wm * 64 + m * 16 + er;
            #pragma unroll
            for (int n = 0; n < 8; n++) {
                int col = bn + wn * 64 + n * 8 + ec;
                *(float2*)(C + (size_t)row0 * N + col)       = make_float2(acc[m][n][0], acc[m][n][1]);
                *(float2*)(C + (size_t)(row0 + 8) * N + col) = make_float2(acc[m][n][2], acc[m][n][3]);
            }
        }
    } else {
        const int part = bn >> 11;   // 0=q, 1=k, 2=v
        #pragma unroll
        for (int m = 0; m < 4; m++) {
            int rowa = bm + wm * 64 + m * 16 + er;
            #pragma unroll
            for (int rr = 0; rr < 2; rr++) {
                int row = rowa + rr * 8;
                int l = row & 2047;
                #pragma unroll
                for (int n = 0; n < 8; n++) {
                    int col = bn + wn * 64 + n * 8 + ec;
                    float v0 = acc[m][n][2 * rr], v1 = acc[m][n][2 * rr + 1];
                    if (part < 2) {
                        int i = (col & 127) >> 1;
                        float c = ct[l * 64 + i], s = st_[l * 64 + i];
                        float r0 = v0 * c - v1 * s;
                        float r1 = v1 * c + v0 * s;
                        if (part == 0) { r0 *= QSCALE; r1 *= QSCALE; }
                        v0 = r0; v1 = r1;
                    }
                    *(__half2*)(O16 + (size_t)row * E3_ + col) = __floats2half2_rn(v0, v1);
                }
            }
        }
    }
}

// ---------------------------------------------------------------------------
// V transpose (fp16 in/out): qkv16 v-part -> vt16 [b,h,128,l]
// ---------------------------------------------------------------------------
__global__ __launch_bounds__(256) void vtrans(const __half* __restrict__ qkv16,
                                              __half* __restrict__ vt16)
{
    __shared__ float vt[32][129];
    const int bh = blockIdx.y;
    const int b = bh >> 4, h = bh & 15;
    const int l0 = blockIdx.x * 32;
    const int tid = threadIdx.x;
    const int lane = tid & 31;
    const int hd0 = lane * 4;

    #pragma unroll
    for (int pass = 0; pass < 4; pass++) {
        int ll = (tid >> 5) + pass * 8;
        size_t src = (size_t)(b * L_ + l0 + ll) * E3_ + 2 * D_ + h * HD_ + hd0;
        __half2 a = *(const __half2*)(qkv16 + src);
        __half2 c = *(const __half2*)(qkv16 + src + 2);
        vt[ll][hd0]     = __half2float(a.x); vt[ll][hd0 + 1] = __half2float(a.y);
        vt[ll][hd0 + 2] = __half2float(c.x); vt[ll][hd0 + 3] = __half2float(c.y);
    }
    __syncthreads();

    const int r = tid >> 1;
    const int lh = (tid & 1) * 16;
    size_t vbase = ((size_t)bh * HD_ + r) * L_ + l0 + lh;
    #pragma unroll
    for (int j = 0; j < 16; j += 2) {
        *(__half2*)(vt16 + vbase + j) =
            __floats2half2_rn(vt[lh + j][r], vt[lh + j + 1][r]);
    }
}

// ---------------------------------------------------------------------------
// Flash attention, fp16 single-term mma, 64 q-rows/CTA, 2 CTAs/SM (R16-proven).
// NEW: logits arrive pre-scaled by scale*log2e (folded into Q), so softmax is
// pure exp2 (no per-element multiplies); o-rescale skipped when max unchanged.
// SMEM: Q 16KB | 2 stages x (K 16K | Vt 16K) = 80KB.
// ---------------------------------------------------------------------------
#define ATT_SMEM 81920

__global__ __launch_bounds__(128, 2) void flash_mma(
    const __half* __restrict__ qkv16, const __half* __restrict__ vt16,
    __half* __restrict__ y)
{
    extern __shared__ char smem[];
    const uint32_t sb = smem_u32(smem);
    const int tid = threadIdx.x, wid = tid >> 5, lane = tid & 31;
    const int bh = blockIdx.y;
    const int b = bh >> 4, h = bh & 15;
    const int q0 = (gridDim.x - 1 - blockIdx.x) * 64;
    const int NB = q0 / 64 + 1;

    const __half* qb = qkv16 + (size_t)b * L_ * E3_ + h * HD_;
    const __half* kb = qb + D_;
    const size_t vbase = (size_t)bh * HD_ * L_;

    #pragma unroll
    for (int it = 0; it < 8; it++) {
        int idx = tid + 128 * it;
        int c = idx & 15, r = idx >> 4;
        const __half* src = qb + (size_t)(q0 + r) * E3_ + c * 8;
        CP16(sb + (c >> 3) * 8192 + SWZ((uint32_t)(r * 128 + (c & 7) * 16)), src);
    }
    auto load_kv = [&](int kb_i, int s) {
        const uint32_t st0 = sb + 16384 + s * 32768;
        const int k0 = kb_i * 64;
        #pragma unroll
        for (int it = 0; it < 8; it++) {
            int idx = tid + 128 * it;
            int c = idx & 15, r = idx >> 4;
            const __half* src = kb + (size_t)(k0 + r) * E3_ + c * 8;
            CP16(st0 + (c >> 3) * 8192 + SWZ((uint32_t)(r * 128 + (c & 7) * 16)), src);
        }
        #pragma unroll
        for (int it = 0; it < 8; it++) {
            int idx = tid + 128 * it;
            int c = idx & 7, r = idx >> 3;
            const __half* src = vt16 + vbase + (size_t)r * L_ + k0 + c * 8;
            CP16(st0 + 16384 + SWZ((uint32_t)(r * 128 + c * 16)), src);
        }
        CP_COMMIT();
    };

    load_kv(0, 0);
    if (NB > 1) load_kv(1, 1);

    float o[16][4];
    #pragma unroll
    for (int n = 0; n < 16; n++)
        #pragma unroll
        for (int v = 0; v < 4; v++) o[n][v] = 0.f;
    float m0 = -1e30f, m1 = -1e30f, l0 = 0.f, l1 = 0.f;

    const int a_row = wid * 16 + (lane & 15);
    const uint32_t a_kb = (lane >> 4) << 4;
    const int b_row = (lane & 7) + ((lane >> 4) << 3);
    const uint32_t b_kb = ((lane >> 3) & 1) << 4;
    const int row0 = q0 + wid * 16 + (lane >> 2);
    const int ec = (lane & 3) * 2;

    for (int kbi = 0; kbi < NB; kbi++) {
        const int s = kbi & 1;
        if (kbi == NB - 1) CP_WAIT0(); else CP_WAIT1();
        __syncthreads();
        const uint32_t st0 = sb + 16384 + s * 32768;
        const int k0 = kbi * 64;

        // ---- S2 = (Q*qscale) K^T  (base-2 logits) ----
        float sc[8][4];
        #pragma unroll
        for (int n = 0; n < 8; n++)
            #pragma unroll
            for (int v = 0; v < 4; v++) sc[n][v] = 0.f;

        #pragma unroll
        for (int half = 0; half < 2; half++)
            #pragma unroll
            for (int ks = 0; ks < 4; ks++) {
                uint32_t qo = sb + half * 8192 + SWZ((uint32_t)(a_row * 128 + ks * 32 + a_kb));
                uint32_t aQ[4];
                LDSM4(aQ[0], aQ[1], aQ[2], aQ[3], qo);
                #pragma unroll
                for (int p = 0; p < 4; p++) {
                    uint32_t ko = st0 + half * 8192 + SWZ((uint32_t)((b_row + p * 16) * 128 + ks * 32 + b_kb));
                    uint32_t bH[4];
                    LDSM4(bH[0], bH[1], bH[2], bH[3], ko);
                    mma_f16(sc[2*p],   aQ, bH[0], bH[1]);
                    mma_f16(sc[2*p+1], aQ, bH[2], bH[3]);
                }
            }

        // ---- causal mask (diagonal tile only) ----
        if (kbi == NB - 1) {
            #pragma unroll
            for (int n = 0; n < 8; n++)
                #pragma unroll
                for (int v = 0; v < 4; v++) {
                    int col = k0 + n * 8 + ec + (v & 1);
                    int row = row0 + ((v >= 2) ? 8 : 0);
                    if (col > row) sc[n][v] = -1e30f;
                }
        }

        // ---- online softmax (base-2) ----
        float mx0 = -1e30f, mx1 = -1e30f;
        #pragma unroll
        for (int n = 0; n < 8; n++) {
            mx0 = fmaxf(mx0, fmaxf(sc[n][0], sc[n][1]));
            mx1 = fmaxf(mx1, fmaxf(sc[n][2], sc[n][3]));
        }
        mx0 = fmaxf(mx0, __shfl_xor_sync(0xffffffffu, mx0, 1));
        mx0 = fmaxf(mx0, __shfl_xor_sync(0xffffffffu, mx0, 2));
        mx1 = fmaxf(mx1, __shfl_xor_sync(0xffffffffu, mx1, 1));
        mx1 = fmaxf(mx1, __shfl_xor_sync(0xffffffffu, mx1, 2));
        bool up0 = mx0 > m0, up1 = mx1 > m1;
        float al0 = 1.f, al1 = 1.f;
        if (up0) { al0 = exp2f(m0 - mx0); m0 = mx0; }
        if (up1) { al1 = exp2f(m1 - mx1); m1 = mx1; }

        float ps0 = 0.f, ps1 = 0.f;
        #pragma unroll
        for (int n = 0; n < 8; n++) {
            float p0 = exp2f(sc[n][0] - m0), p1 = exp2f(sc[n][1] - m0);
            float p2 = exp2f(sc[n][2] - m1), p3 = exp2f(sc[n][3] - m1);
            sc[n][0] = p0; sc[n][1] = p1; sc[n][2] = p2; sc[n][3] = p3;
            ps0 += p0 + p1; ps1 += p2 + p3;
        }
        l0 = l0 * al0 + ps0;
        l1 = l1 * al1 + ps1;

        if (__any_sync(0xffffffffu, up0 | up1)) {
            #pragma unroll
            for (int n = 0; n < 16; n++) {
                o[n][0] *= al0; o[n][1] *= al0; o[n][2] *= al1; o[n][3] *= al1;
            }
        }

        // ---- O += P V ----
        #pragma unroll
        for (int kc = 0; kc < 4; kc++) {
            uint32_t aP[4];
            aP[0] = pack_f16(sc[2*kc][0],   sc[2*kc][1]);
            aP[1] = pack_f16(sc[2*kc][2],   sc[2*kc][3]);
            aP[2] = pack_f16(sc[2*kc+1][0], sc[2*kc+1][1]);
            aP[3] = pack_f16(sc[2*kc+1][2], sc[2*kc+1][3]);
            #pragma unroll
            for (int p = 0; p < 8; p++) {
                uint32_t vo = st0 + 16384 + SWZ((uint32_t)((b_row + p * 16) * 128 + kc * 32 + b_kb));
                uint32_t bH[4];
                LDSM4(bH[0], bH[1], bH[2], bH[3], vo);
                mma_f16(o[2*p],   aP, bH[0], bH[1]);
                mma_f16(o[2*p+1], aP, bH[2], bH[3]);
            }
        }
        __syncthreads();
        if (kbi + 2 < NB) load_kv(kbi + 2, s);
    }

    l0 += __shfl_xor_sync(0xffffffffu, l0, 1);
    l0 += __shfl_xor_sync(0xffffffffu, l0, 2);
    l1 += __shfl_xor_sync(0xffffffffu, l1, 1);
    l1 += __shfl_xor_sync(0xffffffffu, l1, 2);
    float i0 = 1.f / l0, i1 = 1.f / l1;
    const size_t rbase = (size_t)(b * L_ + row0) * D_ + h * HD_ + ec;
    #pragma unroll
    for (int n = 0; n < 16; n++) {
        size_t o0 = rbase + n * 8;
        size_t o1 = o0 + 8 * (size_t)D_;
        *(__half2*)(y + o0) = __floats2half2_rn(o[n][0] * i0, o[n][1] * i0);
        *(__half2*)(y + o1) = __floats2half2_rn(o[n][2] * i1, o[n][3] * i1);
    }
}

// ---------------------------------------------------------------------------
extern "C" void kernel_launch(void* const* d_in, const int* in_sizes, int n_in,
                              void* d_out, int out_size)
{
    const float* x     = (const float*)d_in[0];
    const float* w_qkv = (const float*)d_in[1];
    const float* w_o   = (const float*)d_in[2];
    float* out = (float*)d_out;

    float *ct, *st;
    __half *qkv16, *x16, *wq16, *wo16, *y16, *vt16;
    cudaGetSymbolAddress((void**)&qkv16, g_qkv16);
    cudaGetSymbolAddress((void**)&ct,    g_cos); cudaGetSymbolAddress((void**)&st, g_sin);
    cudaGetSymbolAddress((void**)&x16,   g_x16);
    cudaGetSymbolAddress((void**)&wq16,  g_wq16);
    cudaGetSymbolAddress((void**)&wo16,  g_wo16);
    cudaGetSymbolAddress((void**)&y16,   g_y16);
    cudaGetSymbolAddress((void**)&vt16,  g_vt16);

    cudaFuncSetAttribute(gemm_f16<0>, cudaFuncAttributeMaxDynamicSharedMemorySize, GEMM_SMEM);
    cudaFuncSetAttribute(gemm_f16<1>, cudaFuncAttributeMaxDynamicSharedMemorySize, GEMM_SMEM);
    cudaFuncSetAttribute(flash_mma,   cudaFuncAttributeMaxDynamicSharedMemorySize, ATT_SMEM);

    prep_all<<<(PREP_N4 + 255) / 256, 256>>>(x, w_qkv, w_o, x16, wq16, wo16, ct, st);

    // 1) qkv = x @ w_qkv^T, fused RoPE + Q-prescale + fp16 store
    gemm_f16<1><<<(M_ / BM) * (E3_ / BN), 256, GEMM_SMEM>>>(
        x16, wq16, nullptr, qkv16, ct, st, M_, E3_, D_);

    // 2) V transpose (fp16)
    vtrans<<<dim3(L_ / 32, B_ * H_), 256>>>(qkv16, vt16);

    // 3) causal flash attention (base-2 softmax) -> y fp16
    flash_mma<<<dim3(L_ / 64, B_ * H_), 128, ATT_SMEM>>>(qkv16, vt16, y16);

    // 4) out = y @ w_o^T (fp32 out)
    gemm_f16<0><<<(M_ / BM) * (D_ / BN), 256, GEMM_SMEM>>>(
        y16, wo16, out, nullptr, nullptr, nullptr, M_, D_, D_);
}